// round 5
// baseline (speedup 1.0000x reference)
#include <cuda_runtime.h>
#include <cuda_bf16.h>
#include <cstdint>

// ============================================================================
// scores[b,l] = sum_d tanh( (enc[b,l,:] @ W1_e)[d] + dec_proj[b,d] + b1[d] ) * w2[d]
// out = softmax(scores, axis=-1).  B=32, LIN=2048, E=D=512, nd=1024.
//
// bf16 mma.sync.m16n8k16 GEMM, fused tanh+dot(w2) epilogue.
// R5: high-MLP prep (fat conv blocks, dec/transpose scheduled first),
// earlier prefetch issue in main loop. Main kernel keeps R4 occ-2 structure.
// ============================================================================

// Scratch device globals (no allocation allowed)
__device__ __align__(16) __nv_bfloat16 g_encb[65536u * 512u]; // 64 MB bf16 A
__device__ __align__(16) __nv_bfloat16 g_W1Tb[512 * 512];     // W1_e^T bf16 [d][k]
__device__ __align__(16) float g_dpp[128 * 512];              // dec_proj split-K partials
__device__ __align__(16) float g_spart[4u * 65536u];          // per-colunit partial scores

// ---------------------------------------------------------------------------
// helpers
// ---------------------------------------------------------------------------
__device__ __forceinline__ uint32_t smem_u32(const void* p) {
    uint32_t a;
    asm("{ .reg .u64 t; cvta.to.shared.u64 t, %1; cvt.u32.u64 %0, t; }" : "=r"(a) : "l"(p));
    return a;
}
__device__ __forceinline__ void cp_async16(uint32_t sdst, const void* gsrc) {
    asm volatile("cp.async.cg.shared.global [%0], [%1], 16;" :: "r"(sdst), "l"(gsrc) : "memory");
}
#define CP_COMMIT() asm volatile("cp.async.commit_group;" ::: "memory")
#define CP_WAIT(n)  asm volatile("cp.async.wait_group %0;" :: "n"(n) : "memory")

__device__ __forceinline__ float tanh_fast(float x) {
    float t;
    asm("tanh.approx.f32 %0, %1;" : "=f"(t) : "f"(x));
    return t;
}
__device__ __forceinline__ void ldmatrix_x4(uint32_t r[4], uint32_t addr) {
    asm volatile("ldmatrix.sync.aligned.m8n8.x4.shared.b16 {%0,%1,%2,%3}, [%4];"
                 : "=r"(r[0]), "=r"(r[1]), "=r"(r[2]), "=r"(r[3]) : "r"(addr));
}
__device__ __forceinline__ void mma_bf16(float c[4], const uint32_t a[4], const uint32_t b[2]) {
    asm volatile(
        "mma.sync.aligned.m16n8k16.row.col.f32.bf16.bf16.f32 "
        "{%0,%1,%2,%3}, {%4,%5,%6,%7}, {%8,%9}, {%0,%1,%2,%3};"
        : "+f"(c[0]), "+f"(c[1]), "+f"(c[2]), "+f"(c[3])
        : "r"(a[0]), "r"(a[1]), "r"(a[2]), "r"(a[3]), "r"(b[0]), "r"(b[1]));
}

// ---------------------------------------------------------------------------
// Kernel P: fused prep. Blocks scheduled latency-bound-first:
//   [0,128):    dec_proj split-K (8 accumulators, MLP 8)
//   [128,384):  W1_e transpose -> bf16 [d][k]
//   [384,4480): enc fp32 -> bf16 (8 independent float4 loads per thread)
// ---------------------------------------------------------------------------
__global__ void __launch_bounds__(256) prep_kernel(
    const float* __restrict__ enc, const float* __restrict__ W1,
    const float* __restrict__ dh) {
    int bid = blockIdx.x, tid = threadIdx.x;
    if (bid >= 384) {
        // ---- enc fp32 -> bf16: 4096 blocks x 8192 floats ----
        size_t base = (size_t)(bid - 384) * 8192 + tid * 4;
        float4 v[8];
#pragma unroll
        for (int p = 0; p < 8; p++)
            v[p] = *(const float4*)(enc + base + (size_t)p * 1024);
#pragma unroll
        for (int p = 0; p < 8; p += 2) {
            __nv_bfloat162 q0 = __float22bfloat162_rn({v[p].x,     v[p].y});
            __nv_bfloat162 q1 = __float22bfloat162_rn({v[p].z,     v[p].w});
            __nv_bfloat162 q2 = __float22bfloat162_rn({v[p + 1].x, v[p + 1].y});
            __nv_bfloat162 q3 = __float22bfloat162_rn({v[p + 1].z, v[p + 1].w});
            uint4 o;
            o.x = *(uint32_t*)&q0; o.y = *(uint32_t*)&q1;
            o.z = *(uint32_t*)&q2; o.w = *(uint32_t*)&q3;
            // two float4 (p, p+1) at float offsets base+p*1024, base+(p+1)*1024
            *(uint4*)(g_encb + base + (size_t)p * 1024) = o;
            // note: p and p+1 are 1024 floats apart; must store separately
        }
        // fix: the pair-combined store above is wrong for strided pairs; redo safely
        return;
    } else if (bid >= 128) {
        // ---- W1_e transpose -> bf16 ----
        __shared__ float tile[32][33];
        int v = bid - 128;
        int d0 = (v & 15) * 32, k0 = (v >> 4) * 32;
        int tx = tid & 31, ty = tid >> 5;
#pragma unroll
        for (int j = 0; j < 32; j += 8)
            tile[ty + j][tx] = W1[(size_t)(1024 + k0 + ty + j) * 512 + d0 + tx];
        __syncthreads();
#pragma unroll
        for (int j = 0; j < 32; j += 8)
            g_W1Tb[(size_t)(d0 + ty + j) * 512 + k0 + tx] = __float2bfloat16_rn(tile[tx][ty + j]);
    } else {
        // ---- dec_proj split-K partials, MLP 8 ----
        __shared__ float sdf[256];
        int bq = bid;
        int b = bq >> 2, q = bq & 3;
        sdf[tid] = dh[b * 1024 + q * 256 + tid];
        __syncthreads();
        const float* w0 = W1 + (size_t)(q * 256) * 512 + tid;
        const float* w1 = w0 + 256;
        float a[8] = {0.f, 0.f, 0.f, 0.f, 0.f, 0.f, 0.f, 0.f};
#pragma unroll 2
        for (int k = 0; k < 256; k += 4) {
            a[0] = fmaf(sdf[k + 0], w0[(size_t)(k + 0) * 512], a[0]);
            a[1] = fmaf(sdf[k + 1], w0[(size_t)(k + 1) * 512], a[1]);
            a[2] = fmaf(sdf[k + 2], w0[(size_t)(k + 2) * 512], a[2]);
            a[3] = fmaf(sdf[k + 3], w0[(size_t)(k + 3) * 512], a[3]);
            a[4] = fmaf(sdf[k + 0], w1[(size_t)(k + 0) * 512], a[4]);
            a[5] = fmaf(sdf[k + 1], w1[(size_t)(k + 1) * 512], a[5]);
            a[6] = fmaf(sdf[k + 2], w1[(size_t)(k + 2) * 512], a[6]);
            a[7] = fmaf(sdf[k + 3], w1[(size_t)(k + 3) * 512], a[7]);
        }
        g_dpp[(size_t)bq * 512 + tid]       = (a[0] + a[1]) + (a[2] + a[3]);
        g_dpp[(size_t)bq * 512 + tid + 256] = (a[4] + a[5]) + (a[6] + a[7]);
    }
}

// Correct conv kernel (separate, contiguous per-thread 32-float chunk):
// 4096 blocks x 256 thr; thread handles 8 consecutive float4 (32 floats),
// stores 4 uint4 (pairs of adjacent float4 -> 8 bf16 each).
__global__ void __launch_bounds__(256) conv_kernel(const float* __restrict__ enc) {
    size_t base = ((size_t)blockIdx.x * 256 + threadIdx.x) * 32;
    float4 v[8];
#pragma unroll
    for (int p = 0; p < 8; p++)
        v[p] = *(const float4*)(enc + base + p * 4);
#pragma unroll
    for (int p = 0; p < 8; p += 2) {
        __nv_bfloat162 q0 = __float22bfloat162_rn({v[p].x,     v[p].y});
        __nv_bfloat162 q1 = __float22bfloat162_rn({v[p].z,     v[p].w});
        __nv_bfloat162 q2 = __float22bfloat162_rn({v[p + 1].x, v[p + 1].y});
        __nv_bfloat162 q3 = __float22bfloat162_rn({v[p + 1].z, v[p + 1].w});
        uint4 o;
        o.x = *(uint32_t*)&q0; o.y = *(uint32_t*)&q1;
        o.z = *(uint32_t*)&q2; o.w = *(uint32_t*)&q3;
        *(uint4*)(g_encb + base + p * 4) = o;
    }
}

// ---------------------------------------------------------------------------
// Kernel M: fused bf16 GEMM + tanh + dot(w2).
// Grid 2048 units: bid = rowchunk*4 + colunit (colunit inner -> A L2 reuse).
// Unit = 128 rows x 128 cols. 8 warps (2m x 4n), warp tile 64x32, acc 64 regs.
// K = 8 tiles of 64; 3 stages x (A 16KB + B 16KB); occupancy 2.
// ---------------------------------------------------------------------------
static constexpr uint32_t AUX_SZ   = 4096;
static constexpr uint32_t STAGE_SZ = 32768;                  // A 16KB + B 16KB
static constexpr uint32_t SMEM_MAIN = AUX_SZ + 3 * STAGE_SZ; // 102400

__global__ void __launch_bounds__(256, 2)
attn_main_kernel(const float* __restrict__ b1, const float* __restrict__ w2) {
    extern __shared__ char sm[];
    float* add_s = (float*)sm;                 // 128 f
    float* w2_s  = (float*)(sm + 512);         // 128 f
    float* spart = (float*)(sm + 1024);        // 4 x 128 f
    const uint32_t stages_u = smem_u32(sm + AUX_SZ);

    const int tid  = threadIdx.x;
    const int lane = tid & 31, wid = tid >> 5;
    const int wm   = wid & 1, wn = wid >> 1;   // 2m x 4n warp grid
    const int quad = lane >> 2, qlane = lane & 3;
    const int lane7 = lane & 7;

    const int cu = blockIdx.x & 3;             // column unit (inner -> L2 A reuse)
    const int rc = blockIdx.x >> 2;            // row chunk 0..511
    const size_t row0 = (size_t)rc * 128;
    const __nv_bfloat16* gA = g_encb + row0 * 512;
    const __nv_bfloat16* gB = g_W1Tb + (size_t)(cu * 128) * 512;

    const int b = rc >> 4;                     // batch for dec_proj
    if (tid < 128) {
        int d = cu * 128 + tid;
        float s0 = g_dpp[(size_t)(b * 4 + 0) * 512 + d] + g_dpp[(size_t)(b * 4 + 1) * 512 + d];
        float s1 = g_dpp[(size_t)(b * 4 + 2) * 512 + d] + g_dpp[(size_t)(b * 4 + 3) * 512 + d];
        add_s[tid] = s0 + s1 + b1[d];
        w2_s[tid]  = w2[d];
    }

    // prefetch k-tile t into stage t%3 (A and B are both 128 rows x 128B)
    auto prefetch = [&](int t) {
        uint32_t sA = stages_u + (uint32_t)(t % 3) * STAGE_SZ;
        uint32_t sB = sA + 16384;
        const __nv_bfloat16* srcA = gA + t * 64;
        const __nv_bfloat16* srcB = gB + t * 64;
#pragma unroll
        for (int p = 0; p < 4; p++) {
            int slot = tid + p * 256;
            int r = slot >> 3, blk = slot & 7;
            uint32_t off = (uint32_t)(r * 128 + ((blk ^ (r & 7)) << 4));
            cp_async16(sA + off, srcA + (size_t)r * 512 + blk * 8);
            cp_async16(sB + off, srcB + (size_t)r * 512 + blk * 8);
        }
        CP_COMMIT();
    };

    prefetch(0); prefetch(1);

    float acc[4][4][4];
#pragma unroll
    for (int mf = 0; mf < 4; mf++)
#pragma unroll
        for (int nf = 0; nf < 4; nf++)
#pragma unroll
            for (int k = 0; k < 4; k++) acc[mf][nf][k] = 0.f;

    const uint32_t a_row = (uint32_t)(wm * 64 + ((lane >> 3) & 1) * 8 + lane7);
    const uint32_t b_row = (uint32_t)(wn * 32 + (lane >> 4) * 8 + lane7);

    for (int i = 0; i < 8; i++) {
        CP_WAIT(1);
        __syncthreads();
        // issue next prefetch EARLY (stage (i+2)%3 == (i-1)%3, safe post-barrier)
        if (i + 2 < 8) prefetch(i + 2);
        else CP_COMMIT();                      // keep group accounting uniform

        uint32_t sA = stages_u + (uint32_t)(i % 3) * STAGE_SZ;
        uint32_t sB = sA + 16384;

#pragma unroll
        for (int kf = 0; kf < 4; kf++) {
            uint32_t afr[4][4], bfr[4][2];
            uint32_t ablk = (uint32_t)(((kf * 2 + (lane >> 4)) ^ lane7) << 4);
            uint32_t bblk = (uint32_t)(((kf * 2 + ((lane >> 3) & 1)) ^ lane7) << 4);
#pragma unroll
            for (int mf = 0; mf < 4; mf++)
                ldmatrix_x4(afr[mf], sA + (a_row + mf * 16) * 128 + ablk);
#pragma unroll
            for (int j = 0; j < 2; j++) {
                uint32_t r[4];
                ldmatrix_x4(r, sB + (b_row + j * 16) * 128 + bblk);
                bfr[2 * j][0] = r[0];     bfr[2 * j][1] = r[1];
                bfr[2 * j + 1][0] = r[2]; bfr[2 * j + 1][1] = r[3];
            }
#pragma unroll
            for (int mf = 0; mf < 4; mf++)
#pragma unroll
                for (int nf = 0; nf < 4; nf++)
                    mma_bf16(acc[mf][nf], afr[mf], bfr[nf]);
        }
    }

    // ---- epilogue: tanh(acc + add) * w2, reduce over 128 cols ----
#pragma unroll
    for (int mf = 0; mf < 4; mf++) {
        float s0 = 0.f, s1 = 0.f;
#pragma unroll
        for (int nf = 0; nf < 4; nf++) {
            int c = wn * 32 + nf * 8 + qlane * 2;
            float a0 = add_s[c], a1 = add_s[c + 1];
            float v0 = w2_s[c],  v1 = w2_s[c + 1];
            s0 = fmaf(tanh_fast(acc[mf][nf][0] + a0), v0, s0);
            s0 = fmaf(tanh_fast(acc[mf][nf][1] + a1), v1, s0);
            s1 = fmaf(tanh_fast(acc[mf][nf][2] + a0), v0, s1);
            s1 = fmaf(tanh_fast(acc[mf][nf][3] + a1), v1, s1);
        }
        s0 += __shfl_xor_sync(0xffffffffu, s0, 1);
        s0 += __shfl_xor_sync(0xffffffffu, s0, 2);
        s1 += __shfl_xor_sync(0xffffffffu, s1, 1);
        s1 += __shfl_xor_sync(0xffffffffu, s1, 2);
        if (qlane == 0) {
            int r = wm * 64 + mf * 16 + quad;
            spart[wn * 128 + r]     = s0;
            spart[wn * 128 + r + 8] = s1;
        }
    }
    __syncthreads();
    if (tid < 128)
        g_spart[(size_t)cu * 65536 + row0 + tid] =
            spart[tid] + spart[128 + tid] + spart[256 + tid] + spart[384 + tid];
}

// ---------------------------------------------------------------------------
// Kernel S: sum 4 partials + row softmax over 2048. 32 blocks x 256 threads.
// ---------------------------------------------------------------------------
__global__ void softmax_kernel(float* __restrict__ out) {
    __shared__ float red[256];
    int b = blockIdx.x, t = threadIdx.x;
    float v[8];
    float vmax = -1e30f;
#pragma unroll
    for (int j = 0; j < 8; j++) {
        size_t idx = (size_t)b * 2048 + j * 256 + t;
        v[j] = g_spart[idx] + g_spart[65536 + idx] + g_spart[131072 + idx] + g_spart[196608 + idx];
        vmax = fmaxf(vmax, v[j]);
    }
    red[t] = vmax; __syncthreads();
    for (int s = 128; s > 0; s >>= 1) {
        if (t < s) red[t] = fmaxf(red[t], red[t + s]);
        __syncthreads();
    }
    vmax = red[0]; __syncthreads();
    float sum = 0.f;
#pragma unroll
    for (int j = 0; j < 8; j++) {
        v[j] = __expf(v[j] - vmax);
        sum += v[j];
    }
    red[t] = sum; __syncthreads();
    for (int s = 128; s > 0; s >>= 1) {
        if (t < s) red[t] += red[t + s];
        __syncthreads();
    }
    float inv = 1.0f / red[0];
#pragma unroll
    for (int j = 0; j < 8; j++)
        out[b * 2048 + j * 256 + t] = v[j] * inv;
}

// ---------------------------------------------------------------------------
// kernel_launch — inputs: d_hidden, encoder_outputs, W1, b1, w2
// ---------------------------------------------------------------------------
extern "C" void kernel_launch(void* const* d_in, const int* in_sizes, int n_in,
                              void* d_out, int out_size) {
    const float* dh  = (const float*)d_in[0];  // (32, 2, 512)
    const float* enc = (const float*)d_in[1];  // (32, 2048, 512)
    const float* W1  = (const float*)d_in[2];  // (1536, 512)
    const float* b1  = (const float*)d_in[3];  // (512,)
    const float* w2  = (const float*)d_in[4];  // (512,)
    float* out = (float*)d_out;                // (32, 2048)

    cudaFuncSetAttribute(attn_main_kernel, cudaFuncAttributeMaxDynamicSharedMemorySize,
                         (int)SMEM_MAIN);

    prep_kernel<<<384, 256>>>(enc, W1, dh);    // dec_proj + transpose only
    conv_kernel<<<4096, 256>>>(enc);           // enc fp32 -> bf16, MLP 8
    attn_main_kernel<<<2048, 256, SMEM_MAIN>>>(b1, w2);
    softmax_kernel<<<32, 256>>>(out);
}

// round 6
// speedup vs baseline: 1.1783x; 1.1783x over previous
#include <cuda_runtime.h>
#include <cuda_bf16.h>
#include <cstdint>

// ============================================================================
// scores[b,l] = sum_d tanh( (enc[b,l,:] @ W1_e)[d] + dec_proj[b,d] + b1[d] ) * w2[d]
// out = softmax(scores, axis=-1).  B=32, LIN=2048, E=D=512, nd=1024.
//
// bf16 mma.sync.m16n8k16 GEMM, fused tanh+dot(w2) epilogue.
// R6: main kernel = exact R4 (best measured). Prep = single kernel,
// latency-bound blocks first, conv branch coalesced with MLP 8.
// ============================================================================

// Scratch device globals (no allocation allowed)
__device__ __align__(16) __nv_bfloat16 g_encb[65536u * 512u]; // 64 MB bf16 A
__device__ __align__(16) __nv_bfloat16 g_W1Tb[512 * 512];     // W1_e^T bf16 [d][k]
__device__ __align__(16) float g_dpp[128 * 512];              // dec_proj split-K partials
__device__ __align__(16) float g_spart[4u * 65536u];          // per-colunit partial scores

// ---------------------------------------------------------------------------
// helpers
// ---------------------------------------------------------------------------
__device__ __forceinline__ uint32_t smem_u32(const void* p) {
    uint32_t a;
    asm("{ .reg .u64 t; cvta.to.shared.u64 t, %1; cvt.u32.u64 %0, t; }" : "=r"(a) : "l"(p));
    return a;
}
__device__ __forceinline__ void cp_async16(uint32_t sdst, const void* gsrc) {
    asm volatile("cp.async.cg.shared.global [%0], [%1], 16;" :: "r"(sdst), "l"(gsrc) : "memory");
}
#define CP_COMMIT() asm volatile("cp.async.commit_group;" ::: "memory")
#define CP_WAIT(n)  asm volatile("cp.async.wait_group %0;" :: "n"(n) : "memory")

__device__ __forceinline__ float tanh_fast(float x) {
    float t;
    asm("tanh.approx.f32 %0, %1;" : "=f"(t) : "f"(x));
    return t;
}
__device__ __forceinline__ void ldmatrix_x4(uint32_t r[4], uint32_t addr) {
    asm volatile("ldmatrix.sync.aligned.m8n8.x4.shared.b16 {%0,%1,%2,%3}, [%4];"
                 : "=r"(r[0]), "=r"(r[1]), "=r"(r[2]), "=r"(r[3]) : "r"(addr));
}
__device__ __forceinline__ void mma_bf16(float c[4], const uint32_t a[4], const uint32_t b[2]) {
    asm volatile(
        "mma.sync.aligned.m16n8k16.row.col.f32.bf16.bf16.f32 "
        "{%0,%1,%2,%3}, {%4,%5,%6,%7}, {%8,%9}, {%0,%1,%2,%3};"
        : "+f"(c[0]), "+f"(c[1]), "+f"(c[2]), "+f"(c[3])
        : "r"(a[0]), "r"(a[1]), "r"(a[2]), "r"(a[3]), "r"(b[0]), "r"(b[1]));
}

// ---------------------------------------------------------------------------
// Kernel P: fused prep, latency-bound classes first.
//   [0,128):    dec_proj split-K (MLP 8)
//   [128,384):  W1_e transpose -> bf16 [d][k]
//   [384,4480): enc fp32 -> bf16, coalesced, 8 independent float4 per thread
// ---------------------------------------------------------------------------
__global__ void __launch_bounds__(256) prep_kernel(
    const float* __restrict__ enc, const float* __restrict__ W1,
    const float* __restrict__ dh) {
    int bid = blockIdx.x, tid = threadIdx.x;
    if (bid >= 384) {
        // block handles 8192 consecutive floats; thread t: float4 at
        // base + t*4 + p*1024 (lane-consecutive -> coalesced; MLP 8)
        size_t base = (size_t)(bid - 384) * 8192 + (size_t)tid * 4;
        float4 v[8];
#pragma unroll
        for (int p = 0; p < 8; p++)
            v[p] = *(const float4*)(enc + base + (size_t)p * 1024);
#pragma unroll
        for (int p = 0; p < 8; p++) {
            __nv_bfloat162 q0 = __float22bfloat162_rn({v[p].x, v[p].y});
            __nv_bfloat162 q1 = __float22bfloat162_rn({v[p].z, v[p].w});
            uint2 o;
            o.x = *(uint32_t*)&q0; o.y = *(uint32_t*)&q1;
            *(uint2*)(g_encb + base + (size_t)p * 1024) = o;
        }
    } else if (bid >= 128) {
        // ---- W1_e transpose -> bf16 ----
        __shared__ float tile[32][33];
        int v = bid - 128;
        int d0 = (v & 15) * 32, k0 = (v >> 4) * 32;
        int tx = tid & 31, ty = tid >> 5;
#pragma unroll
        for (int j = 0; j < 32; j += 8)
            tile[ty + j][tx] = W1[(size_t)(1024 + k0 + ty + j) * 512 + d0 + tx];
        __syncthreads();
#pragma unroll
        for (int j = 0; j < 32; j += 8)
            g_W1Tb[(size_t)(d0 + ty + j) * 512 + k0 + tx] = __float2bfloat16_rn(tile[tx][ty + j]);
    } else {
        // ---- dec_proj split-K partials, MLP 8 ----
        __shared__ float sdf[256];
        int bq = bid;
        int b = bq >> 2, q = bq & 3;
        sdf[tid] = dh[b * 1024 + q * 256 + tid];
        __syncthreads();
        const float* w0 = W1 + (size_t)(q * 256) * 512 + tid;
        const float* w1 = w0 + 256;
        float a[8] = {0.f, 0.f, 0.f, 0.f, 0.f, 0.f, 0.f, 0.f};
#pragma unroll 2
        for (int k = 0; k < 256; k += 4) {
            a[0] = fmaf(sdf[k + 0], w0[(size_t)(k + 0) * 512], a[0]);
            a[1] = fmaf(sdf[k + 1], w0[(size_t)(k + 1) * 512], a[1]);
            a[2] = fmaf(sdf[k + 2], w0[(size_t)(k + 2) * 512], a[2]);
            a[3] = fmaf(sdf[k + 3], w0[(size_t)(k + 3) * 512], a[3]);
            a[4] = fmaf(sdf[k + 0], w1[(size_t)(k + 0) * 512], a[4]);
            a[5] = fmaf(sdf[k + 1], w1[(size_t)(k + 1) * 512], a[5]);
            a[6] = fmaf(sdf[k + 2], w1[(size_t)(k + 2) * 512], a[6]);
            a[7] = fmaf(sdf[k + 3], w1[(size_t)(k + 3) * 512], a[7]);
        }
        g_dpp[(size_t)bq * 512 + tid]       = (a[0] + a[1]) + (a[2] + a[3]);
        g_dpp[(size_t)bq * 512 + tid + 256] = (a[4] + a[5]) + (a[6] + a[7]);
    }
}

// ---------------------------------------------------------------------------
// Kernel M: fused bf16 GEMM + tanh + dot(w2). (exact R4 version)
// Grid 2048 units: bid = rowchunk*4 + colunit (colunit inner -> A L2 reuse).
// Unit = 128 rows x 128 cols. 8 warps (2m x 4n), warp tile 64x32, acc 64 regs.
// K = 8 tiles of 64; 3 stages x (A 16KB + B 16KB); occupancy 2.
// ---------------------------------------------------------------------------
static constexpr uint32_t AUX_SZ   = 4096;
static constexpr uint32_t STAGE_SZ = 32768;                  // A 16KB + B 16KB
static constexpr uint32_t SMEM_MAIN = AUX_SZ + 3 * STAGE_SZ; // 102400

__global__ void __launch_bounds__(256, 2)
attn_main_kernel(const float* __restrict__ b1, const float* __restrict__ w2) {
    extern __shared__ char sm[];
    float* add_s = (float*)sm;                 // 128 f
    float* w2_s  = (float*)(sm + 512);         // 128 f
    float* spart = (float*)(sm + 1024);        // 4 x 128 f
    const uint32_t stages_u = smem_u32(sm + AUX_SZ);

    const int tid  = threadIdx.x;
    const int lane = tid & 31, wid = tid >> 5;
    const int wm   = wid & 1, wn = wid >> 1;   // 2m x 4n warp grid
    const int quad = lane >> 2, qlane = lane & 3;
    const int lane7 = lane & 7;

    const int cu = blockIdx.x & 3;             // column unit (inner -> L2 A reuse)
    const int rc = blockIdx.x >> 2;            // row chunk 0..511
    const size_t row0 = (size_t)rc * 128;
    const __nv_bfloat16* gA = g_encb + row0 * 512;
    const __nv_bfloat16* gB = g_W1Tb + (size_t)(cu * 128) * 512;

    const int b = rc >> 4;                     // batch for dec_proj
    if (tid < 128) {
        int d = cu * 128 + tid;
        float s0 = g_dpp[(size_t)(b * 4 + 0) * 512 + d] + g_dpp[(size_t)(b * 4 + 1) * 512 + d];
        float s1 = g_dpp[(size_t)(b * 4 + 2) * 512 + d] + g_dpp[(size_t)(b * 4 + 3) * 512 + d];
        add_s[tid] = s0 + s1 + b1[d];
        w2_s[tid]  = w2[d];
    }

    // prefetch k-tile t into stage t%3 (A and B are both 128 rows x 128B)
    auto prefetch = [&](int t) {
        uint32_t sA = stages_u + (uint32_t)(t % 3) * STAGE_SZ;
        uint32_t sB = sA + 16384;
        const __nv_bfloat16* srcA = gA + t * 64;
        const __nv_bfloat16* srcB = gB + t * 64;
#pragma unroll
        for (int p = 0; p < 4; p++) {
            int slot = tid + p * 256;
            int r = slot >> 3, blk = slot & 7;
            uint32_t off = (uint32_t)(r * 128 + ((blk ^ (r & 7)) << 4));
            cp_async16(sA + off, srcA + (size_t)r * 512 + blk * 8);
            cp_async16(sB + off, srcB + (size_t)r * 512 + blk * 8);
        }
        CP_COMMIT();
    };

    prefetch(0); prefetch(1);

    float acc[4][4][4];
#pragma unroll
    for (int mf = 0; mf < 4; mf++)
#pragma unroll
        for (int nf = 0; nf < 4; nf++)
#pragma unroll
            for (int k = 0; k < 4; k++) acc[mf][nf][k] = 0.f;

    const uint32_t a_row = (uint32_t)(wm * 64 + ((lane >> 3) & 1) * 8 + lane7);
    const uint32_t b_row = (uint32_t)(wn * 32 + (lane >> 4) * 8 + lane7);

    for (int i = 0; i < 8; i++) {
        CP_WAIT(1);
        __syncthreads();
        uint32_t sA = stages_u + (uint32_t)(i % 3) * STAGE_SZ;
        uint32_t sB = sA + 16384;

#pragma unroll
        for (int kf = 0; kf < 4; kf++) {
            uint32_t afr[4][4], bfr[4][2];
            uint32_t ablk = (uint32_t)(((kf * 2 + (lane >> 4)) ^ lane7) << 4);
            uint32_t bblk = (uint32_t)(((kf * 2 + ((lane >> 3) & 1)) ^ lane7) << 4);
#pragma unroll
            for (int mf = 0; mf < 4; mf++)
                ldmatrix_x4(afr[mf], sA + (a_row + mf * 16) * 128 + ablk);
#pragma unroll
            for (int j = 0; j < 2; j++) {
                uint32_t r[4];
                ldmatrix_x4(r, sB + (b_row + j * 16) * 128 + bblk);
                bfr[2 * j][0] = r[0];     bfr[2 * j][1] = r[1];
                bfr[2 * j + 1][0] = r[2]; bfr[2 * j + 1][1] = r[3];
            }
#pragma unroll
            for (int mf = 0; mf < 4; mf++)
#pragma unroll
                for (int nf = 0; nf < 4; nf++)
                    mma_bf16(acc[mf][nf], afr[mf], bfr[nf]);
        }

        if (i + 2 < 8) prefetch(i + 2);
        else CP_COMMIT();                      // keep group accounting uniform
    }

    // ---- epilogue: tanh(acc + add) * w2, reduce over 128 cols ----
#pragma unroll
    for (int mf = 0; mf < 4; mf++) {
        float s0 = 0.f, s1 = 0.f;
#pragma unroll
        for (int nf = 0; nf < 4; nf++) {
            int c = wn * 32 + nf * 8 + qlane * 2;
            float a0 = add_s[c], a1 = add_s[c + 1];
            float v0 = w2_s[c],  v1 = w2_s[c + 1];
            s0 = fmaf(tanh_fast(acc[mf][nf][0] + a0), v0, s0);
            s0 = fmaf(tanh_fast(acc[mf][nf][1] + a1), v1, s0);
            s1 = fmaf(tanh_fast(acc[mf][nf][2] + a0), v0, s1);
            s1 = fmaf(tanh_fast(acc[mf][nf][3] + a1), v1, s1);
        }
        s0 += __shfl_xor_sync(0xffffffffu, s0, 1);
        s0 += __shfl_xor_sync(0xffffffffu, s0, 2);
        s1 += __shfl_xor_sync(0xffffffffu, s1, 1);
        s1 += __shfl_xor_sync(0xffffffffu, s1, 2);
        if (qlane == 0) {
            int r = wm * 64 + mf * 16 + quad;
            spart[wn * 128 + r]     = s0;
            spart[wn * 128 + r + 8] = s1;
        }
    }
    __syncthreads();
    if (tid < 128)
        g_spart[(size_t)cu * 65536 + row0 + tid] =
            spart[tid] + spart[128 + tid] + spart[256 + tid] + spart[384 + tid];
}

// ---------------------------------------------------------------------------
// Kernel S: sum 4 partials + row softmax over 2048. 32 blocks x 256 threads.
// ---------------------------------------------------------------------------
__global__ void softmax_kernel(float* __restrict__ out) {
    __shared__ float red[256];
    int b = blockIdx.x, t = threadIdx.x;
    float v[8];
    float vmax = -1e30f;
#pragma unroll
    for (int j = 0; j < 8; j++) {
        size_t idx = (size_t)b * 2048 + j * 256 + t;
        v[j] = g_spart[idx] + g_spart[65536 + idx] + g_spart[131072 + idx] + g_spart[196608 + idx];
        vmax = fmaxf(vmax, v[j]);
    }
    red[t] = vmax; __syncthreads();
    for (int s = 128; s > 0; s >>= 1) {
        if (t < s) red[t] = fmaxf(red[t], red[t + s]);
        __syncthreads();
    }
    vmax = red[0]; __syncthreads();
    float sum = 0.f;
#pragma unroll
    for (int j = 0; j < 8; j++) {
        v[j] = __expf(v[j] - vmax);
        sum += v[j];
    }
    red[t] = sum; __syncthreads();
    for (int s = 128; s > 0; s >>= 1) {
        if (t < s) red[t] += red[t + s];
        __syncthreads();
    }
    float inv = 1.0f / red[0];
#pragma unroll
    for (int j = 0; j < 8; j++)
        out[b * 2048 + j * 256 + t] = v[j] * inv;
}

// ---------------------------------------------------------------------------
// kernel_launch — inputs: d_hidden, encoder_outputs, W1, b1, w2
// ---------------------------------------------------------------------------
extern "C" void kernel_launch(void* const* d_in, const int* in_sizes, int n_in,
                              void* d_out, int out_size) {
    const float* dh  = (const float*)d_in[0];  // (32, 2, 512)
    const float* enc = (const float*)d_in[1];  // (32, 2048, 512)
    const float* W1  = (const float*)d_in[2];  // (1536, 512)
    const float* b1  = (const float*)d_in[3];  // (512,)
    const float* w2  = (const float*)d_in[4];  // (512,)
    float* out = (float*)d_out;                // (32, 2048)

    cudaFuncSetAttribute(attn_main_kernel, cudaFuncAttributeMaxDynamicSharedMemorySize,
                         (int)SMEM_MAIN);

    prep_kernel<<<4480, 256>>>(enc, W1, dh);
    attn_main_kernel<<<2048, 256, SMEM_MAIN>>>(b1, w2);
    softmax_kernel<<<32, 256>>>(out);
}